// round 1
// baseline (speedup 1.0000x reference)
#include <cuda_runtime.h>
#include <math.h>

#define TSEQ 2048
#define NBATCH 2
#define CDIM 1024
#define NHEAD 16
#define DHEAD 64
#define MROWS (TSEQ*NBATCH)   // 4096

// Scratch (allocation-free rule: __device__ globals)
__device__ float g_qh[NBATCH*NHEAD*TSEQ*DHEAD];
__device__ float g_kh[NBATCH*NHEAD*TSEQ*DHEAD];
__device__ float g_vh[NBATCH*NHEAD*TSEQ*DHEAD];
__device__ float g_y [MROWS*CDIM];

// ---------------------------------------------------------------------------
// NT SGEMM: C[m][n] = sum_k A[m][k]*B[n][k] + bias[n]
// A: (4096,1024) row-major, B: (1024,1024) row-major. Tile 128x128x8, 256 thr,
// 8x8 per-thread register tile. qkv_layout writes [n][h][t][d] scatter.
// ---------------------------------------------------------------------------
__device__ __forceinline__ void gemm_nt_128(
    const float* __restrict__ A, const float* __restrict__ B,
    const float* __restrict__ bias, float* __restrict__ O, bool qkv_layout)
{
    __shared__ float As[8][128];
    __shared__ float Bs[8][128];
    float acc[8][8];
#pragma unroll
    for (int i = 0; i < 8; i++)
#pragma unroll
        for (int j = 0; j < 8; j++) acc[i][j] = 0.f;

    const int tid = threadIdx.x;
    const int tr  = tid >> 4;        // 0..15
    const int tc  = tid & 15;        // 0..15
    const int m0  = blockIdx.y * 128;
    const int n0  = blockIdx.x * 128;
    const int lr  = tid >> 1;        // 0..127
    const int lk  = (tid & 1) << 2;  // 0 or 4
    const float* Ap = A + (size_t)(m0 + lr) * CDIM + lk;
    const float* Bp = B + (size_t)(n0 + lr) * CDIM + lk;

    for (int k0 = 0; k0 < CDIM; k0 += 8) {
        float4 a4 = *(const float4*)(Ap + k0);
        float4 b4 = *(const float4*)(Bp + k0);
        As[lk+0][lr] = a4.x; As[lk+1][lr] = a4.y;
        As[lk+2][lr] = a4.z; As[lk+3][lr] = a4.w;
        Bs[lk+0][lr] = b4.x; Bs[lk+1][lr] = b4.y;
        Bs[lk+2][lr] = b4.z; Bs[lk+3][lr] = b4.w;
        __syncthreads();
#pragma unroll
        for (int kk = 0; kk < 8; kk++) {
            float4 a0 = *(const float4*)&As[kk][tr*8];
            float4 a1 = *(const float4*)&As[kk][tr*8+4];
            float4 b0 = *(const float4*)&Bs[kk][tc*8];
            float4 b1 = *(const float4*)&Bs[kk][tc*8+4];
            float am[8] = {a0.x,a0.y,a0.z,a0.w,a1.x,a1.y,a1.z,a1.w};
            float bn[8] = {b0.x,b0.y,b0.z,b0.w,b1.x,b1.y,b1.z,b1.w};
#pragma unroll
            for (int i = 0; i < 8; i++)
#pragma unroll
                for (int j = 0; j < 8; j++)
                    acc[i][j] = fmaf(am[i], bn[j], acc[i][j]);
        }
        __syncthreads();
    }

    const int co0 = n0 + tc*8;
    float bv[8];
#pragma unroll
    for (int j = 0; j < 8; j++) bv[j] = bias[co0 + j];

    if (!qkv_layout) {
#pragma unroll
        for (int i = 0; i < 8; i++) {
            int m = m0 + tr*8 + i;
            float* op = O + (size_t)m * CDIM + co0;
#pragma unroll
            for (int j = 0; j < 8; j++) op[j] = acc[i][j] + bv[j];
        }
    } else {
        // out index: qh[((nb*H + h)*T + t)*Dh + d], m=(t,nb), co=(h,d)
        const int h  = co0 >> 6;
        const int d0 = co0 & 63;   // tc*8 stays within one head (64 | n0)
#pragma unroll
        for (int i = 0; i < 8; i++) {
            int m  = m0 + tr*8 + i;
            int t  = m >> 1;
            int nb = m & 1;
            float* op = O + ((size_t)(nb*NHEAD + h)*TSEQ + t)*DHEAD + d0;
#pragma unroll
            for (int j = 0; j < 8; j++) op[j] = acc[i][j] + bv[j];
        }
    }
}

__global__ __launch_bounds__(256) void proj3_kernel(
    const float* __restrict__ xq, const float* __restrict__ xk, const float* __restrict__ xv,
    const float* __restrict__ Wq, const float* __restrict__ Wk, const float* __restrict__ Wv,
    const float* __restrict__ bq, const float* __restrict__ bk, const float* __restrict__ bv)
{
    const int z = blockIdx.z;
    const float* A  = (z == 0) ? xq : (z == 1) ? xk : xv;
    const float* B  = (z == 0) ? Wq : (z == 1) ? Wk : Wv;
    const float* bb = (z == 0) ? bq : (z == 1) ? bk : bv;
    float* O        = (z == 0) ? g_qh : (z == 1) ? g_kh : g_vh;
    gemm_nt_128(A, B, bb, O, true);
}

__global__ __launch_bounds__(256) void oproj_kernel(
    const float* __restrict__ Wo, const float* __restrict__ bo, float* __restrict__ out)
{
    gemm_nt_128(g_y, Wo, bo, out, false);
}

// ---------------------------------------------------------------------------
// Flash attention, 64x64 tiles. Mask: |i-j|<=128 OR j<key_length[n].
// Tiles with neither condition are skipped. 256 threads, 4x4 micro-tiles.
// Qt/KPt are stored [d][row] so inner loops use conflict-free float4 LDS.
// KPt buffer is reused for transposed P after softmax.
// ---------------------------------------------------------------------------
__global__ __launch_bounds__(256) void attn_kernel(const int* __restrict__ key_length)
{
    __shared__ float Qt [64][64];  // [d][r]
    __shared__ float KPt[64][64];  // K as [d][c]; reused as P as [c][r]
    __shared__ float Vs [64][64];  // [k][d]

    const int tid = threadIdx.x;
    const int tr  = tid >> 4;      // 0..15 -> rows tr*4..tr*4+3
    const int tc  = tid & 15;      // 0..15 -> cols tc*4..tc*4+3
    const int n   = blockIdx.z, h = blockIdx.y;
    const int q0  = blockIdx.x * 64;
    const int keylen = key_length[n];

    const float* Qb = g_qh + (size_t)(n*NHEAD + h) * TSEQ * DHEAD;
    const float* Kb = g_kh + (size_t)(n*NHEAD + h) * TSEQ * DHEAD;
    const float* Vb = g_vh + (size_t)(n*NHEAD + h) * TSEQ * DHEAD;

    const int lrow = tid >> 4;        // 0..15
    const int ld   = (tid & 15) << 2; // 0..60

#pragma unroll
    for (int rr = 0; rr < 4; rr++) {
        int r = rr*16 + lrow;
        float4 qv = *(const float4*)(Qb + (size_t)(q0 + r)*DHEAD + ld);
        Qt[ld+0][r] = qv.x; Qt[ld+1][r] = qv.y;
        Qt[ld+2][r] = qv.z; Qt[ld+3][r] = qv.w;
    }

    float mrow[4], lsum[4], accO[4][4];
#pragma unroll
    for (int i = 0; i < 4; i++) {
        mrow[i] = -INFINITY; lsum[i] = 0.f;
#pragma unroll
        for (int j = 0; j < 4; j++) accO[i][j] = 0.f;
    }

    for (int kt0 = 0; kt0 < TSEQ; kt0 += 64) {
        // skip tiles entirely masked: not in band and not in prefix
        const bool band = (kt0 >= q0 - 191) && (kt0 <= q0 + 191);
        if (!(kt0 < keylen) && !band) continue;

        __syncthreads();  // prior-iteration reads of KPt/Vs complete
#pragma unroll
        for (int rr = 0; rr < 4; rr++) {
            int r = rr*16 + lrow;
            float4 kv = *(const float4*)(Kb + (size_t)(kt0 + r)*DHEAD + ld);
            KPt[ld+0][r] = kv.x; KPt[ld+1][r] = kv.y;
            KPt[ld+2][r] = kv.z; KPt[ld+3][r] = kv.w;
            float4 vv = *(const float4*)(Vb + (size_t)(kt0 + r)*DHEAD + ld);
            *(float4*)&Vs[r][ld] = vv;
        }
        __syncthreads();

        // S = Q @ K^T  (4x4 per thread)
        float s[4][4];
#pragma unroll
        for (int i = 0; i < 4; i++)
#pragma unroll
            for (int j = 0; j < 4; j++) s[i][j] = 0.f;

#pragma unroll 8
        for (int d = 0; d < 64; d++) {
            float4 qv = *(const float4*)&Qt[d][tr*4];
            float4 kv = *(const float4*)&KPt[d][tc*4];
            float qa[4] = {qv.x, qv.y, qv.z, qv.w};
            float ka[4] = {kv.x, kv.y, kv.z, kv.w};
#pragma unroll
            for (int i = 0; i < 4; i++)
#pragma unroll
                for (int j = 0; j < 4; j++)
                    s[i][j] = fmaf(qa[i], ka[j], s[i][j]);
        }

        // mask + scale
        const bool full = (kt0 + 64 <= keylen) ||
                          ((kt0 - q0 <= 64) && (q0 - kt0 <= 64));
        if (full) {
#pragma unroll
            for (int i = 0; i < 4; i++)
#pragma unroll
                for (int j = 0; j < 4; j++) s[i][j] *= 0.125f;
        } else {
#pragma unroll
            for (int i = 0; i < 4; i++) {
                int ig = q0 + tr*4 + i;
#pragma unroll
                for (int j = 0; j < 4; j++) {
                    int jg = kt0 + tc*4 + j;
                    bool ok = (jg < keylen) ||
                              ((ig - jg <= 128) && (jg - ig <= 128));
                    s[i][j] = ok ? s[i][j] * 0.125f : -1e9f;
                }
            }
        }

        // online softmax (row reductions across the 16 tc-threads of each row
        // live in the same half-warp: xor on lane bits 0..3)
#pragma unroll
        for (int i = 0; i < 4; i++) {
            float rm = fmaxf(fmaxf(s[i][0], s[i][1]), fmaxf(s[i][2], s[i][3]));
            rm = fmaxf(rm, __shfl_xor_sync(0xffffffffu, rm, 1));
            rm = fmaxf(rm, __shfl_xor_sync(0xffffffffu, rm, 2));
            rm = fmaxf(rm, __shfl_xor_sync(0xffffffffu, rm, 4));
            rm = fmaxf(rm, __shfl_xor_sync(0xffffffffu, rm, 8));
            float mnew = fmaxf(mrow[i], rm);
            float corr = __expf(mrow[i] - mnew);
            float rs = 0.f;
#pragma unroll
            for (int j = 0; j < 4; j++) {
                s[i][j] = __expf(s[i][j] - mnew);
                rs += s[i][j];
            }
            rs += __shfl_xor_sync(0xffffffffu, rs, 1);
            rs += __shfl_xor_sync(0xffffffffu, rs, 2);
            rs += __shfl_xor_sync(0xffffffffu, rs, 4);
            rs += __shfl_xor_sync(0xffffffffu, rs, 8);
            lsum[i] = lsum[i] * corr + rs;
            mrow[i] = mnew;
#pragma unroll
            for (int j = 0; j < 4; j++) accO[i][j] *= corr;
        }

        __syncthreads();  // everyone done reading K from KPt
        // store P transposed: KPt[c][r] = P[r][c]
#pragma unroll
        for (int i = 0; i < 4; i++)
#pragma unroll
            for (int j = 0; j < 4; j++)
                KPt[tc*4 + j][tr*4 + i] = s[i][j];
        __syncthreads();

        // O += P @ V
#pragma unroll 8
        for (int kk = 0; kk < 64; kk++) {
            float4 pv = *(const float4*)&KPt[kk][tr*4];
            float4 vv = *(const float4*)&Vs[kk][tc*4];
            float pa[4] = {pv.x, pv.y, pv.z, pv.w};
            float va[4] = {vv.x, vv.y, vv.z, vv.w};
#pragma unroll
            for (int i = 0; i < 4; i++)
#pragma unroll
                for (int j = 0; j < 4; j++)
                    accO[i][j] = fmaf(pa[i], va[j], accO[i][j]);
        }
    }

    // epilogue: y[(t*N + n)*C + h*64 + d] = O/l
#pragma unroll
    for (int i = 0; i < 4; i++) {
        float inv = 1.f / lsum[i];
        int t = q0 + tr*4 + i;
        float4 o4 = make_float4(accO[i][0]*inv, accO[i][1]*inv,
                                accO[i][2]*inv, accO[i][3]*inv);
        *(float4*)(g_y + (size_t)(t*NBATCH + n)*CDIM + h*DHEAD + tc*4) = o4;
    }
}

// ---------------------------------------------------------------------------
extern "C" void kernel_launch(void* const* d_in, const int* in_sizes, int n_in,
                              void* d_out, int out_size) {
    const float* q  = (const float*)d_in[0];
    const float* k  = (const float*)d_in[1];
    const float* v  = (const float*)d_in[2];
    const float* Wq = (const float*)d_in[3];
    const float* bq = (const float*)d_in[4];
    const float* Wk = (const float*)d_in[5];
    const float* bk = (const float*)d_in[6];
    const float* Wv = (const float*)d_in[7];
    const float* bv = (const float*)d_in[8];
    const float* Wo = (const float*)d_in[9];
    const float* bo = (const float*)d_in[10];
    const int* keylen = (const int*)d_in[11];
    float* out = (float*)d_out;

    // 3 input projections (z-batched), scatter into [n][h][t][d]
    proj3_kernel<<<dim3(CDIM/128, MROWS/128, 3), 256>>>(
        q, k, v, Wq, Wk, Wv, bq, bk, bv);

    // masked flash attention -> g_y in (t, n, c) layout
    attn_kernel<<<dim3(TSEQ/64, NHEAD, NBATCH), 256>>>(keylen);

    // output projection
    oproj_kernel<<<dim3(CDIM/128, MROWS/128, 1), 256>>>(Wo, bo, out);
}

// round 5
// speedup vs baseline: 1.6806x; 1.6806x over previous
#include <cuda_runtime.h>
#include <cuda_bf16.h>
#include <math.h>
#include <stdint.h>

#define TSEQ 2048
#define NBATCH 2
#define CDIM 1024
#define NHEAD 16
#define DHEAD 64
#define MROWS (TSEQ*NBATCH)   // 4096

#define KCH 64                // k-chunk held in smem
#define SKA 72                // smem row stride in halves (bank-conflict-free)
#define TILE_H (128*SKA)      // halves per tile
#define SMEM_G (4*TILE_H*2)   // bytes: Ah, Al, Bh, Bl

// ---------------- scratch (__device__ globals; no allocation allowed) -------
__device__ float g_qh[NBATCH*NHEAD*TSEQ*DHEAD];
__device__ float g_kh[NBATCH*NHEAD*TSEQ*DHEAD];
__device__ float g_vh[NBATCH*NHEAD*TSEQ*DHEAD];
__device__ float g_y [MROWS*CDIM];
__device__ __nv_bfloat16 g_xh[3u*MROWS*CDIM];
__device__ __nv_bfloat16 g_xl[3u*MROWS*CDIM];
__device__ __nv_bfloat16 g_wh[4u*CDIM*CDIM];
__device__ __nv_bfloat16 g_wl[4u*CDIM*CDIM];
__device__ __nv_bfloat16 g_yh[MROWS*CDIM];
__device__ __nv_bfloat16 g_yl[MROWS*CDIM];

// ---------------- PTX helpers ----------------------------------------------
__device__ __forceinline__ uint32_t smem_u32(const void* p) {
    uint32_t r;
    asm("{ .reg .u64 t; cvta.to.shared.u64 t, %1; cvt.u32.u64 %0, t; }"
        : "=r"(r) : "l"(p));
    return r;
}

__device__ __forceinline__ void ldsm4(uint32_t* r, uint32_t addr) {
    asm volatile("ldmatrix.sync.aligned.m8n8.x4.shared.b16 {%0,%1,%2,%3}, [%4];"
                 : "=r"(r[0]), "=r"(r[1]), "=r"(r[2]), "=r"(r[3]) : "r"(addr));
}

__device__ __forceinline__ void mma16816(float* c, const uint32_t* a, const uint32_t* b) {
    asm volatile("mma.sync.aligned.m16n8k16.row.col.f32.bf16.bf16.f32 "
                 "{%0,%1,%2,%3}, {%4,%5,%6,%7}, {%8,%9}, {%0,%1,%2,%3};"
                 : "+f"(c[0]), "+f"(c[1]), "+f"(c[2]), "+f"(c[3])
                 : "r"(a[0]), "r"(a[1]), "r"(a[2]), "r"(a[3]),
                   "r"(b[0]), "r"(b[1]));
}

// ---------------- bf16-split GEMM via mma.sync ------------------------------
// C[m][n] = sum_k A[m][k]*B[n][k] + bias[n]  (Ah*Bh + Al*Bh + Ah*Bl)
// CTA 128x128, 8 warps (2m x 4n), warp tile 64x32, k-chunk 64.
__device__ void gemm_mma(const __nv_bfloat16* __restrict__ Ah,
                         const __nv_bfloat16* __restrict__ Al,
                         const __nv_bfloat16* __restrict__ Bh,
                         const __nv_bfloat16* __restrict__ Bl,
                         const float* __restrict__ bias,
                         float* __restrict__ O, int qkv_mode)
{
    extern __shared__ __nv_bfloat16 sm[];
    const int tid  = threadIdx.x;
    const int lane = tid & 31;
    const int wid  = tid >> 5;
    const int m0   = blockIdx.y * 128;
    const int n0   = blockIdx.x * 128;
    const int wm   = (wid >> 2) * 64;    // warp m-offset in tile
    const int wn   = (wid & 3) * 32;     // warp n-offset in tile

    const uint32_t sbase = smem_u32(sm);
    const uint32_t AH = 0, AL = TILE_H*2, BH = 2*TILE_H*2, BL = 3*TILE_H*2;

    float acc[4][4][4];
#pragma unroll
    for (int mi = 0; mi < 4; mi++)
#pragma unroll
        for (int ni = 0; ni < 4; ni++)
#pragma unroll
            for (int r = 0; r < 4; r++) acc[mi][ni][r] = 0.f;

    const __nv_bfloat16* ArH = Ah + (size_t)m0 * CDIM;
    const __nv_bfloat16* ArL = Al + (size_t)m0 * CDIM;
    const __nv_bfloat16* BrH = Bh + (size_t)n0 * CDIM;
    const __nv_bfloat16* BrL = Bl + (size_t)n0 * CDIM;

    // ldmatrix lane addressing: row = lane&15, col += (lane>>4)*8
    const int lrow = lane & 15;
    const int lhi8 = (lane >> 4) * 8;

    for (int k0 = 0; k0 < CDIM; k0 += KCH) {
        __syncthreads();
        // load 4 tiles of 128x64 bf16 (16B per thread per iter, 4 iters each)
#pragma unroll
        for (int it = 0; it < 4; it++) {
            const int idx = it*256 + tid;
            const int row = idx >> 3;
            const int c16 = (idx & 7) * 8;
            const size_t go = (size_t)row * CDIM + k0 + c16;
            const int so = row*SKA + c16;
            *(uint4*)(sm + 0*TILE_H + so) = *(const uint4*)(ArH + go);
            *(uint4*)(sm + 1*TILE_H + so) = *(const uint4*)(ArL + go);
            *(uint4*)(sm + 2*TILE_H + so) = *(const uint4*)(BrH + go);
            *(uint4*)(sm + 3*TILE_H + so) = *(const uint4*)(BrL + go);
        }
        __syncthreads();

#pragma unroll
        for (int ks = 0; ks < KCH/16; ks++) {
            const int kcol = ks*16 + lhi8;
            uint32_t ah[4][4], al[4][4], bh[4][2], bl[4][2];
#pragma unroll
            for (int mi = 0; mi < 4; mi++) {
                const uint32_t ro = (uint32_t)((wm + mi*16 + lrow)*SKA + kcol) * 2;
                ldsm4(ah[mi], sbase + AH + ro);
                ldsm4(al[mi], sbase + AL + ro);
            }
#pragma unroll
            for (int nj = 0; nj < 2; nj++) {
                const uint32_t ro = (uint32_t)((wn + nj*16 + lrow)*SKA + kcol) * 2;
                uint32_t t[4];
                ldsm4(t, sbase + BH + ro);
                bh[2*nj][0] = t[0]; bh[2*nj+1][0] = t[1];
                bh[2*nj][1] = t[2]; bh[2*nj+1][1] = t[3];
                ldsm4(t, sbase + BL + ro);
                bl[2*nj][0] = t[0]; bl[2*nj+1][0] = t[1];
                bl[2*nj][1] = t[2]; bl[2*nj+1][1] = t[3];
            }
#pragma unroll
            for (int mi = 0; mi < 4; mi++)
#pragma unroll
                for (int ni = 0; ni < 4; ni++) {
                    mma16816(acc[mi][ni], ah[mi], bh[ni]);
                    mma16816(acc[mi][ni], al[mi], bh[ni]);
                    mma16816(acc[mi][ni], ah[mi], bl[ni]);
                }
        }
    }

    // ---- epilogue: c-frag thread mapping: rows g,g+8; cols 2t,2t+1 ---------
    const int cg = lane >> 2;        // 0..7
    const int ct = lane & 3;         // 0..3
#pragma unroll
    for (int mi = 0; mi < 4; mi++) {
#pragma unroll
        for (int ni = 0; ni < 4; ni++) {
            const int c = n0 + wn + ni*8 + ct*2;
            const float b0 = bias[c], b1 = bias[c+1];
#pragma unroll
            for (int half = 0; half < 2; half++) {
                const int m = m0 + wm + mi*16 + cg + half*8;
                const float v0 = acc[mi][ni][half*2+0] + b0;
                const float v1 = acc[mi][ni][half*2+1] + b1;
                if (qkv_mode) {
                    const int t = m >> 1, nb = m & 1;
                    const int h = c >> 6, d = c & 63;
                    float* op = O + ((size_t)(nb*NHEAD + h)*TSEQ + t)*DHEAD + d;
                    *(float2*)op = make_float2(v0, v1);
                } else {
                    *(float2*)(O + (size_t)m*CDIM + c) = make_float2(v0, v1);
                }
            }
        }
    }
}

__global__ __launch_bounds__(256, 2) void proj3_tc(const float* __restrict__ bq,
                                                   const float* __restrict__ bk,
                                                   const float* __restrict__ bv)
{
    const int z = blockIdx.z;
    const size_t xo = (size_t)z * MROWS * CDIM;
    const size_t wo = (size_t)z * CDIM * CDIM;
    const float* bias = (z == 0) ? bq : (z == 1) ? bk : bv;
    float* O = (z == 0) ? g_qh : (z == 1) ? g_kh : g_vh;
    gemm_mma(g_xh + xo, g_xl + xo, g_wh + wo, g_wl + wo, bias, O, 1);
}

__global__ __launch_bounds__(256, 2) void oproj_tc(const float* __restrict__ bo,
                                                   float* __restrict__ out)
{
    gemm_mma(g_yh, g_yl, g_wh + (size_t)3*CDIM*CDIM, g_wl + (size_t)3*CDIM*CDIM,
             bo, out, 0);
}

// ---------------- bf16 split kernels ----------------------------------------
__device__ __forceinline__ void split4(const float* __restrict__ s,
                                       __nv_bfloat16* __restrict__ h,
                                       __nv_bfloat16* __restrict__ l, size_t i)
{
    float4 v = *(const float4*)(s + i);
    float x[4] = {v.x, v.y, v.z, v.w};
    __nv_bfloat16 hv[4], lv[4];
#pragma unroll
    for (int j = 0; j < 4; j++) {
        hv[j] = __float2bfloat16_rn(x[j]);
        lv[j] = __float2bfloat16_rn(x[j] - __bfloat162float(hv[j]));
    }
    *(__nv_bfloat162*)(h + i)     = __halves2bfloat162(hv[0], hv[1]);
    *(__nv_bfloat162*)(h + i + 2) = __halves2bfloat162(hv[2], hv[3]);
    *(__nv_bfloat162*)(l + i)     = __halves2bfloat162(lv[0], lv[1]);
    *(__nv_bfloat162*)(l + i + 2) = __halves2bfloat162(lv[2], lv[3]);
}

__global__ __launch_bounds__(256) void split_x(const float* __restrict__ q,
                                               const float* __restrict__ k,
                                               const float* __restrict__ v)
{
    const int z = blockIdx.z;
    const float* s = (z == 0) ? q : (z == 1) ? k : v;
    const size_t off = (size_t)z * MROWS * CDIM;
    size_t i = ((size_t)blockIdx.x * blockDim.x + threadIdx.x) * 4;
    split4(s, g_xh + off, g_xl + off, i);
}

__global__ __launch_bounds__(256) void split_w(const float* __restrict__ Wq,
                                               const float* __restrict__ Wk,
                                               const float* __restrict__ Wv,
                                               const float* __restrict__ Wo)
{
    const int z = blockIdx.z;
    const float* s = (z == 0) ? Wq : (z == 1) ? Wk : (z == 2) ? Wv : Wo;
    const size_t off = (size_t)z * CDIM * CDIM;
    size_t i = ((size_t)blockIdx.x * blockDim.x + threadIdx.x) * 4;
    split4(s, g_wh + off, g_wl + off, i);
}

__global__ __launch_bounds__(256) void split_y()
{
    size_t i = ((size_t)blockIdx.x * blockDim.x + threadIdx.x) * 4;
    split4(g_y, g_yh, g_yl, i);
}

// ---------------- flash attention (fp32, unchanged) -------------------------
__global__ __launch_bounds__(256) void attn_kernel(const int* __restrict__ key_length)
{
    __shared__ float Qt [64][64];
    __shared__ float KPt[64][64];
    __shared__ float Vs [64][64];

    const int tid = threadIdx.x;
    const int tr  = tid >> 4;
    const int tc  = tid & 15;
    const int n   = blockIdx.z, h = blockIdx.y;
    const int q0  = blockIdx.x * 64;
    const int keylen = key_length[n];

    const float* Qb = g_qh + (size_t)(n*NHEAD + h) * TSEQ * DHEAD;
    const float* Kb = g_kh + (size_t)(n*NHEAD + h) * TSEQ * DHEAD;
    const float* Vb = g_vh + (size_t)(n*NHEAD + h) * TSEQ * DHEAD;

    const int lrow = tid >> 4;
    const int ld   = (tid & 15) << 2;

#pragma unroll
    for (int rr = 0; rr < 4; rr++) {
        int r = rr*16 + lrow;
        float4 qv = *(const float4*)(Qb + (size_t)(q0 + r)*DHEAD + ld);
        Qt[ld+0][r] = qv.x; Qt[ld+1][r] = qv.y;
        Qt[ld+2][r] = qv.z; Qt[ld+3][r] = qv.w;
    }

    float mrow[4], lsum[4], accO[4][4];
#pragma unroll
    for (int i = 0; i < 4; i++) {
        mrow[i] = -INFINITY; lsum[i] = 0.f;
#pragma unroll
        for (int j = 0; j < 4; j++) accO[i][j] = 0.f;
    }

    for (int kt0 = 0; kt0 < TSEQ; kt0 += 64) {
        const bool band = (kt0 >= q0 - 191) && (kt0 <= q0 + 191);
        if (!(kt0 < keylen) && !band) continue;

        __syncthreads();
#pragma unroll
        for (int rr = 0; rr < 4; rr++) {
            int r = rr*16 + lrow;
            float4 kv = *(const float4*)(Kb + (size_t)(kt0 + r)*DHEAD + ld);
            KPt[ld+0][r] = kv.x; KPt[ld+1][r] = kv.y;
            KPt[ld+2][r] = kv.z; KPt[ld+3][r] = kv.w;
            float4 vv = *(const float4*)(Vb + (size_t)(kt0 + r)*DHEAD + ld);
            *(float4*)&Vs[r][ld] = vv;
        }
        __syncthreads();

        float s[4][4];
#pragma unroll
        for (int i = 0; i < 4; i++)
#pragma unroll
            for (int j = 0; j < 4; j++) s[i][j] = 0.f;

#pragma unroll 8
        for (int d = 0; d < 64; d++) {
            float4 qv = *(const float4*)&Qt[d][tr*4];
            float4 kv = *(const float4*)&KPt[d][tc*4];
            float qa[4] = {qv.x, qv.y, qv.z, qv.w};
            float ka[4] = {kv.x, kv.y, kv.z, kv.w};
#pragma unroll
            for (int i = 0; i < 4; i++)
#pragma unroll
                for (int j = 0; j < 4; j++)
                    s[i][j] = fmaf(qa[i], ka[j], s[i][j]);
        }

        const bool full = (kt0 + 64 <= keylen) ||
                          ((kt0 - q0 <= 64) && (q0 - kt0 <= 64));
        if (full) {
#pragma unroll
            for (int i = 0; i < 4; i++)
#pragma unroll
                for (int j = 0; j < 4; j++) s[i][j] *= 0.125f;
        } else {
#pragma unroll
            for (int i = 0; i < 4; i++) {
                int ig = q0 + tr*4 + i;
#pragma unroll
                for (int j = 0; j < 4; j++) {
                    int jg = kt0 + tc*4 + j;
                    bool ok = (jg < keylen) ||
                              ((ig - jg <= 128) && (jg - ig <= 128));
                    s[i][j] = ok ? s[i][j] * 0.125f : -1e9f;
                }
            }
        }

#pragma unroll
        for (int i = 0; i < 4; i++) {
            float rm = fmaxf(fmaxf(s[i][0], s[i][1]), fmaxf(s[i][2], s[i][3]));
            rm = fmaxf(rm, __shfl_xor_sync(0xffffffffu, rm, 1));
            rm = fmaxf(rm, __shfl_xor_sync(0xffffffffu, rm, 2));
            rm = fmaxf(rm, __shfl_xor_sync(0xffffffffu, rm, 4));
            rm = fmaxf(rm, __shfl_xor_sync(0xffffffffu, rm, 8));
            float mnew = fmaxf(mrow[i], rm);
            float corr = __expf(mrow[i] - mnew);
            float rs = 0.f;
#pragma unroll
            for (int j = 0; j < 4; j++) {
                s[i][j] = __expf(s[i][j] - mnew);
                rs += s[i][j];
            }
            rs += __shfl_xor_sync(0xffffffffu, rs, 1);
            rs += __shfl_xor_sync(0xffffffffu, rs, 2);
            rs += __shfl_xor_sync(0xffffffffu, rs, 4);
            rs += __shfl_xor_sync(0xffffffffu, rs, 8);
            lsum[i] = lsum[i] * corr + rs;
            mrow[i] = mnew;
#pragma unroll
            for (int j = 0; j < 4; j++) accO[i][j] *= corr;
        }

        __syncthreads();
#pragma unroll
        for (int i = 0; i < 4; i++)
#pragma unroll
            for (int j = 0; j < 4; j++)
                KPt[tc*4 + j][tr*4 + i] = s[i][j];
        __syncthreads();

#pragma unroll 8
        for (int kk = 0; kk < 64; kk++) {
            float4 pv = *(const float4*)&KPt[kk][tr*4];
            float4 vv = *(const float4*)&Vs[kk][tc*4];
            float pa[4] = {pv.x, pv.y, pv.z, pv.w};
            float va[4] = {vv.x, vv.y, vv.z, vv.w};
#pragma unroll
            for (int i = 0; i < 4; i++)
#pragma unroll
                for (int j = 0; j < 4; j++)
                    accO[i][j] = fmaf(pa[i], va[j], accO[i][j]);
        }
    }

#pragma unroll
    for (int i = 0; i < 4; i++) {
        float inv = 1.f / lsum[i];
        int t = q0 + tr*4 + i;
        float4 o4 = make_float4(accO[i][0]*inv, accO[i][1]*inv,
                                accO[i][2]*inv, accO[i][3]*inv);
        *(float4*)(g_y + (size_t)(t*NBATCH + n)*CDIM + h*DHEAD + tc*4) = o4;
    }
}

// ---------------------------------------------------------------------------
extern "C" void kernel_launch(void* const* d_in, const int* in_sizes, int n_in,
                              void* d_out, int out_size) {
    const float* q  = (const float*)d_in[0];
    const float* k  = (const float*)d_in[1];
    const float* v  = (const float*)d_in[2];
    const float* Wq = (const float*)d_in[3];
    const float* bq = (const float*)d_in[4];
    const float* Wk = (const float*)d_in[5];
    const float* bk = (const float*)d_in[6];
    const float* Wv = (const float*)d_in[7];
    const float* bv = (const float*)d_in[8];
    const float* Wo = (const float*)d_in[9];
    const float* bo = (const float*)d_in[10];
    const int* keylen = (const int*)d_in[11];
    float* out = (float*)d_out;

    cudaFuncSetAttribute(proj3_tc, cudaFuncAttributeMaxDynamicSharedMemorySize, SMEM_G);
    cudaFuncSetAttribute(oproj_tc, cudaFuncAttributeMaxDynamicSharedMemorySize, SMEM_G);

    // split fp32 -> bf16 hi/lo
    split_x<<<dim3(MROWS*CDIM/4/256, 1, 3), 256>>>(q, k, v);
    split_w<<<dim3(CDIM*CDIM/4/256, 1, 4), 256>>>(Wq, Wk, Wv, Wo);

    // q/k/v projections on tensor cores, scatter into [n][h][t][d]
    proj3_tc<<<dim3(CDIM/128, MROWS/128, 3), 256, SMEM_G>>>(bq, bk, bv);

    // masked flash attention -> g_y in (t, n, c) layout
    attn_kernel<<<dim3(TSEQ/64, NHEAD, NBATCH), 256>>>(keylen);

    // split y, output projection on tensor cores
    split_y<<<dim3(MROWS*CDIM/4/256, 1, 1), 256>>>();
    oproj_tc<<<dim3(CDIM/128, MROWS/128, 1), 256, SMEM_G>>>(bo, out);
}

// round 6
// speedup vs baseline: 2.6175x; 1.5575x over previous
#include <cuda_runtime.h>
#include <cuda_bf16.h>
#include <math.h>
#include <stdint.h>

#define TSEQ 2048
#define NBATCH 2
#define CDIM 1024
#define NHEAD 16
#define DHEAD 64
#define MROWS (TSEQ*NBATCH)   // 4096

#define KCH 64                // gemm k-chunk held in smem
#define SKA 72                // smem row stride in halves (bank-conflict-free)
#define TILE_H (128*SKA)      // halves per tile
#define SMEM_G (4*TILE_H*2)   // bytes: Ah, Al, Bh, Bl

// attention tiling
#define BQ 128
#define BK 64
#define SKD 72
#define SMEM_A ((2*BQ*SKD + 2*BK*SKD + 2*DHEAD*SKD)*2)

// ---------------- scratch (__device__ globals; no allocation allowed) -------
__device__ float g_qh[NBATCH*NHEAD*TSEQ*DHEAD];
__device__ float g_kh[NBATCH*NHEAD*TSEQ*DHEAD];
__device__ float g_vh[NBATCH*NHEAD*TSEQ*DHEAD];
__device__ float g_y [MROWS*CDIM];
__device__ __nv_bfloat16 g_xh[3u*MROWS*CDIM];
__device__ __nv_bfloat16 g_xl[3u*MROWS*CDIM];
__device__ __nv_bfloat16 g_wh[4u*CDIM*CDIM];
__device__ __nv_bfloat16 g_wl[4u*CDIM*CDIM];
__device__ __nv_bfloat16 g_yh[MROWS*CDIM];
__device__ __nv_bfloat16 g_yl[MROWS*CDIM];
// attention bf16 split operands
__device__ __nv_bfloat16 g_aqh[NBATCH*NHEAD*TSEQ*DHEAD];
__device__ __nv_bfloat16 g_aql[NBATCH*NHEAD*TSEQ*DHEAD];
__device__ __nv_bfloat16 g_akh[NBATCH*NHEAD*TSEQ*DHEAD];
__device__ __nv_bfloat16 g_akl[NBATCH*NHEAD*TSEQ*DHEAD];
__device__ __nv_bfloat16 g_avth[NBATCH*NHEAD*DHEAD*TSEQ];  // [n][h][d][t]
__device__ __nv_bfloat16 g_avtl[NBATCH*NHEAD*DHEAD*TSEQ];

// ---------------- PTX helpers ----------------------------------------------
__device__ __forceinline__ uint32_t smem_u32(const void* p) {
    uint32_t r;
    asm("{ .reg .u64 t; cvta.to.shared.u64 t, %1; cvt.u32.u64 %0, t; }"
        : "=r"(r) : "l"(p));
    return r;
}

__device__ __forceinline__ void ldsm4(uint32_t* r, uint32_t addr) {
    asm volatile("ldmatrix.sync.aligned.m8n8.x4.shared.b16 {%0,%1,%2,%3}, [%4];"
                 : "=r"(r[0]), "=r"(r[1]), "=r"(r[2]), "=r"(r[3]) : "r"(addr));
}

__device__ __forceinline__ void mma16816(float* c, const uint32_t* a, const uint32_t* b) {
    asm volatile("mma.sync.aligned.m16n8k16.row.col.f32.bf16.bf16.f32 "
                 "{%0,%1,%2,%3}, {%4,%5,%6,%7}, {%8,%9}, {%0,%1,%2,%3};"
                 : "+f"(c[0]), "+f"(c[1]), "+f"(c[2]), "+f"(c[3])
                 : "r"(a[0]), "r"(a[1]), "r"(a[2]), "r"(a[3]),
                   "r"(b[0]), "r"(b[1]));
}

__device__ __forceinline__ uint32_t pf2(float lo, float hi) {  // pack {lo,hi} bf16x2
    uint32_t r;
    asm("cvt.rn.bf16x2.f32 %0, %1, %2;" : "=r"(r) : "f"(hi), "f"(lo));
    return r;
}
// lo-residual pair given the packed hi pair
__device__ __forceinline__ uint32_t plo2(float x0, float x1, uint32_t hp) {
    float h0 = __uint_as_float(hp << 16);
    float h1 = __uint_as_float(hp & 0xffff0000u);
    return pf2(x0 - h0, x1 - h1);
}

// ---------------- bf16-split GEMM via mma.sync ------------------------------
__device__ void gemm_mma(const __nv_bfloat16* __restrict__ Ah,
                         const __nv_bfloat16* __restrict__ Al,
                         const __nv_bfloat16* __restrict__ Bh,
                         const __nv_bfloat16* __restrict__ Bl,
                         const float* __restrict__ bias,
                         float* __restrict__ O, int qkv_mode)
{
    extern __shared__ __nv_bfloat16 sm[];
    const int tid  = threadIdx.x;
    const int lane = tid & 31;
    const int wid  = tid >> 5;
    const int m0   = blockIdx.y * 128;
    const int n0   = blockIdx.x * 128;
    const int wm   = (wid >> 2) * 64;
    const int wn   = (wid & 3) * 32;

    const uint32_t sbase = smem_u32(sm);
    const uint32_t AH = 0, AL = TILE_H*2, BH = 2*TILE_H*2, BL = 3*TILE_H*2;

    float acc[4][4][4];
#pragma unroll
    for (int mi = 0; mi < 4; mi++)
#pragma unroll
        for (int ni = 0; ni < 4; ni++)
#pragma unroll
            for (int r = 0; r < 4; r++) acc[mi][ni][r] = 0.f;

    const __nv_bfloat16* ArH = Ah + (size_t)m0 * CDIM;
    const __nv_bfloat16* ArL = Al + (size_t)m0 * CDIM;
    const __nv_bfloat16* BrH = Bh + (size_t)n0 * CDIM;
    const __nv_bfloat16* BrL = Bl + (size_t)n0 * CDIM;

    const int lrow = lane & 15;
    const int lhi8 = (lane >> 4) * 8;

    for (int k0 = 0; k0 < CDIM; k0 += KCH) {
        __syncthreads();
#pragma unroll
        for (int it = 0; it < 4; it++) {
            const int idx = it*256 + tid;
            const int row = idx >> 3;
            const int c16 = (idx & 7) * 8;
            const size_t go = (size_t)row * CDIM + k0 + c16;
            const int so = row*SKA + c16;
            *(uint4*)(sm + 0*TILE_H + so) = *(const uint4*)(ArH + go);
            *(uint4*)(sm + 1*TILE_H + so) = *(const uint4*)(ArL + go);
            *(uint4*)(sm + 2*TILE_H + so) = *(const uint4*)(BrH + go);
            *(uint4*)(sm + 3*TILE_H + so) = *(const uint4*)(BrL + go);
        }
        __syncthreads();

#pragma unroll
        for (int ks = 0; ks < KCH/16; ks++) {
            const int kcol = ks*16 + lhi8;
            uint32_t ah[4][4], al[4][4], bh[4][2], bl[4][2];
#pragma unroll
            for (int mi = 0; mi < 4; mi++) {
                const uint32_t ro = (uint32_t)((wm + mi*16 + lrow)*SKA + kcol) * 2;
                ldsm4(ah[mi], sbase + AH + ro);
                ldsm4(al[mi], sbase + AL + ro);
            }
#pragma unroll
            for (int nj = 0; nj < 2; nj++) {
                const uint32_t ro = (uint32_t)((wn + nj*16 + lrow)*SKA + kcol) * 2;
                uint32_t t[4];
                ldsm4(t, sbase + BH + ro);
                bh[2*nj][0] = t[0]; bh[2*nj+1][0] = t[1];
                bh[2*nj][1] = t[2]; bh[2*nj+1][1] = t[3];
                ldsm4(t, sbase + BL + ro);
                bl[2*nj][0] = t[0]; bl[2*nj+1][0] = t[1];
                bl[2*nj][1] = t[2]; bl[2*nj+1][1] = t[3];
            }
#pragma unroll
            for (int mi = 0; mi < 4; mi++)
#pragma unroll
                for (int ni = 0; ni < 4; ni++) {
                    mma16816(acc[mi][ni], ah[mi], bh[ni]);
                    mma16816(acc[mi][ni], al[mi], bh[ni]);
                    mma16816(acc[mi][ni], ah[mi], bl[ni]);
                }
        }
    }

    const int cg = lane >> 2;
    const int ct = lane & 3;
#pragma unroll
    for (int mi = 0; mi < 4; mi++) {
#pragma unroll
        for (int ni = 0; ni < 4; ni++) {
            const int c = n0 + wn + ni*8 + ct*2;
            const float b0 = bias[c], b1 = bias[c+1];
#pragma unroll
            for (int half = 0; half < 2; half++) {
                const int m = m0 + wm + mi*16 + cg + half*8;
                const float v0 = acc[mi][ni][half*2+0] + b0;
                const float v1 = acc[mi][ni][half*2+1] + b1;
                if (qkv_mode) {
                    const int t = m >> 1, nb = m & 1;
                    const int h = c >> 6, d = c & 63;
                    float* op = O + ((size_t)(nb*NHEAD + h)*TSEQ + t)*DHEAD + d;
                    *(float2*)op = make_float2(v0, v1);
                } else {
                    *(float2*)(O + (size_t)m*CDIM + c) = make_float2(v0, v1);
                }
            }
        }
    }
}

__global__ __launch_bounds__(256, 2) void proj3_tc(const float* __restrict__ bq,
                                                   const float* __restrict__ bk,
                                                   const float* __restrict__ bv)
{
    const int z = blockIdx.z;
    const size_t xo = (size_t)z * MROWS * CDIM;
    const size_t wo = (size_t)z * CDIM * CDIM;
    const float* bias = (z == 0) ? bq : (z == 1) ? bk : bv;
    float* O = (z == 0) ? g_qh : (z == 1) ? g_kh : g_vh;
    gemm_mma(g_xh + xo, g_xl + xo, g_wh + wo, g_wl + wo, bias, O, 1);
}

__global__ __launch_bounds__(256, 2) void oproj_tc(const float* __restrict__ bo,
                                                   float* __restrict__ out)
{
    gemm_mma(g_yh, g_yl, g_wh + (size_t)3*CDIM*CDIM, g_wl + (size_t)3*CDIM*CDIM,
             bo, out, 0);
}

// ---------------- bf16 split kernels ----------------------------------------
__device__ __forceinline__ void split4(const float* __restrict__ s,
                                       __nv_bfloat16* __restrict__ h,
                                       __nv_bfloat16* __restrict__ l, size_t i)
{
    float4 v = *(const float4*)(s + i);
    float x[4] = {v.x, v.y, v.z, v.w};
    __nv_bfloat16 hv[4], lv[4];
#pragma unroll
    for (int j = 0; j < 4; j++) {
        hv[j] = __float2bfloat16_rn(x[j]);
        lv[j] = __float2bfloat16_rn(x[j] - __bfloat162float(hv[j]));
    }
    *(__nv_bfloat162*)(h + i)     = __halves2bfloat162(hv[0], hv[1]);
    *(__nv_bfloat162*)(h + i + 2) = __halves2bfloat162(hv[2], hv[3]);
    *(__nv_bfloat162*)(l + i)     = __halves2bfloat162(lv[0], lv[1]);
    *(__nv_bfloat162*)(l + i + 2) = __halves2bfloat162(lv[2], lv[3]);
}

__global__ __launch_bounds__(256) void split_x(const float* __restrict__ q,
                                               const float* __restrict__ k,
                                               const float* __restrict__ v)
{
    const int z = blockIdx.z;
    const float* s = (z == 0) ? q : (z == 1) ? k : v;
    const size_t off = (size_t)z * MROWS * CDIM;
    size_t i = ((size_t)blockIdx.x * blockDim.x + threadIdx.x) * 4;
    split4(s, g_xh + off, g_xl + off, i);
}

__global__ __launch_bounds__(256) void split_w(const float* __restrict__ Wq,
                                               const float* __restrict__ Wk,
                                               const float* __restrict__ Wv,
                                               const float* __restrict__ Wo)
{
    const int z = blockIdx.z;
    const float* s = (z == 0) ? Wq : (z == 1) ? Wk : (z == 2) ? Wv : Wo;
    const size_t off = (size_t)z * CDIM * CDIM;
    size_t i = ((size_t)blockIdx.x * blockDim.x + threadIdx.x) * 4;
    split4(s, g_wh + off, g_wl + off, i);
}

__global__ __launch_bounds__(256) void split_y()
{
    size_t i = ((size_t)blockIdx.x * blockDim.x + threadIdx.x) * 4;
    split4(g_y, g_yh, g_yl, i);
}

// split q/k head-layout fp32 -> bf16 hi/lo (same layout)
__global__ __launch_bounds__(256) void split_qk()
{
    const int z = blockIdx.z;
    const float* s = z ? g_kh : g_qh;
    __nv_bfloat16* h = z ? g_akh : g_aqh;
    __nv_bfloat16* l = z ? g_akl : g_aql;
    size_t i = ((size_t)blockIdx.x * blockDim.x + threadIdx.x) * 4;
    split4(s, h, l, i);
}

// v head-layout fp32 [t][d] -> transposed bf16 hi/lo [d][t]
__global__ __launch_bounds__(256) void cvt_v()
{
    __shared__ __align__(16) __nv_bfloat16 sh[64*SKD];
    __shared__ __align__(16) __nv_bfloat16 sl[64*SKD];
    const int tid = threadIdx.x;
    const int n = blockIdx.z, h = blockIdx.y, t0 = blockIdx.x * 64;
    const size_t hb = (size_t)(n*NHEAD + h);
    const float* src = g_vh + (hb*TSEQ + t0)*DHEAD;
#pragma unroll
    for (int it = 0; it < 4; it++) {
        int idx = it*256 + tid;
        int r = idx >> 4;           // t-row 0..63
        int c4 = (idx & 15) * 4;    // d col
        float4 v = *(const float4*)(src + (size_t)r*DHEAD + c4);
        float x[4] = {v.x, v.y, v.z, v.w};
#pragma unroll
        for (int j = 0; j < 4; j++) {
            __nv_bfloat16 hb16 = __float2bfloat16_rn(x[j]);
            sh[(c4+j)*SKD + r] = hb16;
            sl[(c4+j)*SKD + r] = __float2bfloat16_rn(x[j] - __bfloat162float(hb16));
        }
    }
    __syncthreads();
    __nv_bfloat16* oh = g_avth + hb*DHEAD*TSEQ + t0;
    __nv_bfloat16* ol = g_avtl + hb*DHEAD*TSEQ + t0;
#pragma unroll
    for (int it = 0; it < 2; it++) {
        int idx = it*256 + tid;
        int d = idx >> 3;           // 0..63
        int c8 = (idx & 7) * 8;     // t col
        *(uint4*)(oh + (size_t)d*TSEQ + c8) = *(const uint4*)(sh + d*SKD + c8);
        *(uint4*)(ol + (size_t)d*TSEQ + c8) = *(const uint4*)(sl + d*SKD + c8);
    }
}

// ---------------- tensor-core flash attention -------------------------------
// 8 warps x m16 = 128 q rows per CTA; kv tiles of 64; bf16 split QK and PV.
__global__ __launch_bounds__(256) void attn_tc(const int* __restrict__ key_length)
{
    extern __shared__ __nv_bfloat16 as[];
    const int QH = 0, QL = BQ*SKD, KH = 2*BQ*SKD, KL = KH + BK*SKD,
              VH = KL + BK*SKD, VL = VH + DHEAD*SKD;

    const int tid = threadIdx.x, lane = tid & 31, wid = tid >> 5;
    const int n = blockIdx.z, h = blockIdx.y;
    const int q0 = blockIdx.x * BQ;
    const int keylen = key_length[n];
    const size_t hb = (size_t)(n*NHEAD + h);

    const __nv_bfloat16* Qhp = g_aqh + hb*TSEQ*DHEAD;
    const __nv_bfloat16* Qlp = g_aql + hb*TSEQ*DHEAD;
    const __nv_bfloat16* Khp = g_akh + hb*TSEQ*DHEAD;
    const __nv_bfloat16* Klp = g_akl + hb*TSEQ*DHEAD;
    const __nv_bfloat16* Vhp = g_avth + hb*DHEAD*TSEQ;
    const __nv_bfloat16* Vlp = g_avtl + hb*DHEAD*TSEQ;

    // load Q once (128x64 hi+lo)
#pragma unroll
    for (int it = 0; it < 4; it++) {
        int idx = it*256 + tid;
        int r = idx >> 3, c8 = (idx & 7) * 8;
        *(uint4*)(as + QH + r*SKD + c8) = *(const uint4*)(Qhp + (size_t)(q0+r)*DHEAD + c8);
        *(uint4*)(as + QL + r*SKD + c8) = *(const uint4*)(Qlp + (size_t)(q0+r)*DHEAD + c8);
    }

    const uint32_t sb = smem_u32(as);
    const int wm = wid * 16;
    const int lrow = lane & 15, lhi8 = (lane >> 4) * 8;
    const int cg = lane >> 2, ct = lane & 3;
    const int row0 = q0 + wm + cg, row1 = row0 + 8;

    float accO[8][4];
#pragma unroll
    for (int nd = 0; nd < 8; nd++)
#pragma unroll
        for (int r = 0; r < 4; r++) accO[nd][r] = 0.f;
    float m0r = -INFINITY, m1r = -INFINITY, l0 = 0.f, l1 = 0.f;

    for (int kt0 = 0; kt0 < TSEQ; kt0 += BK) {
        const bool band = (kt0 >= q0 - 191) && (kt0 <= q0 + 255);
        if (!(kt0 < keylen) && !band) continue;

        __syncthreads();
#pragma unroll
        for (int it = 0; it < 2; it++) {
            int idx = it*256 + tid;
            int r = idx >> 3, c8 = (idx & 7) * 8;
            *(uint4*)(as + KH + r*SKD + c8) = *(const uint4*)(Khp + (size_t)(kt0+r)*DHEAD + c8);
            *(uint4*)(as + KL + r*SKD + c8) = *(const uint4*)(Klp + (size_t)(kt0+r)*DHEAD + c8);
            *(uint4*)(as + VH + r*SKD + c8) = *(const uint4*)(Vhp + (size_t)r*TSEQ + kt0 + c8);
            *(uint4*)(as + VL + r*SKD + c8) = *(const uint4*)(Vlp + (size_t)r*TSEQ + kt0 + c8);
        }
        __syncthreads();

        // ---- S = Q K^T (split) -----------------------------------------
        float sc[8][4];
#pragma unroll
        for (int nt = 0; nt < 8; nt++)
#pragma unroll
            for (int r = 0; r < 4; r++) sc[nt][r] = 0.f;

#pragma unroll
        for (int ks = 0; ks < 4; ks++) {
            const int kcol = ks*16 + lhi8;
            uint32_t ah[4], al[4];
            const uint32_t ro = (uint32_t)((wm + lrow)*SKD + kcol) * 2;
            ldsm4(ah, sb + (QH)*2 + ro);
            ldsm4(al, sb + (QL)*2 + ro);
#pragma unroll
            for (int nj = 0; nj < 4; nj++) {
                const uint32_t ro2 = (uint32_t)((nj*16 + lrow)*SKD + kcol) * 2;
                uint32_t t[4], bh0[2], bh1[2], bl0[2], bl1[2];
                ldsm4(t, sb + (KH)*2 + ro2);
                bh0[0] = t[0]; bh1[0] = t[1]; bh0[1] = t[2]; bh1[1] = t[3];
                ldsm4(t, sb + (KL)*2 + ro2);
                bl0[0] = t[0]; bl1[0] = t[1]; bl0[1] = t[2]; bl1[1] = t[3];
                mma16816(sc[2*nj],   ah, bh0);
                mma16816(sc[2*nj],   al, bh0);
                mma16816(sc[2*nj],   ah, bl0);
                mma16816(sc[2*nj+1], ah, bh1);
                mma16816(sc[2*nj+1], al, bh1);
                mma16816(sc[2*nj+1], ah, bl1);
            }
        }

        // ---- mask + scale ----------------------------------------------
        const bool full = (kt0 + BK <= keylen) || (kt0 >= q0 - 1 && kt0 <= q0 + 65);
        if (full) {
#pragma unroll
            for (int nt = 0; nt < 8; nt++)
#pragma unroll
                for (int r = 0; r < 4; r++) sc[nt][r] *= 0.125f;
        } else {
#pragma unroll
            for (int nt = 0; nt < 8; nt++) {
                const int jg0 = kt0 + nt*8 + 2*ct;
#pragma unroll
                for (int r = 0; r < 4; r++) {
                    const int ig = (r < 2) ? row0 : row1;
                    const int jg = jg0 + (r & 1);
                    bool ok = (jg < keylen) ||
                              ((ig - jg <= 128) && (jg - ig <= 128));
                    sc[nt][r] = ok ? sc[nt][r] * 0.125f : -1e9f;
                }
            }
        }

        // ---- online softmax (rows row0, row1) --------------------------
        float rm0 = -INFINITY, rm1 = -INFINITY;
#pragma unroll
        for (int nt = 0; nt < 8; nt++) {
            rm0 = fmaxf(rm0, fmaxf(sc[nt][0], sc[nt][1]));
            rm1 = fmaxf(rm1, fmaxf(sc[nt][2], sc[nt][3]));
        }
        rm0 = fmaxf(rm0, __shfl_xor_sync(0xffffffffu, rm0, 1));
        rm0 = fmaxf(rm0, __shfl_xor_sync(0xffffffffu, rm0, 2));
        rm1 = fmaxf(rm1, __shfl_xor_sync(0xffffffffu, rm1, 1));
        rm1 = fmaxf(rm1, __shfl_xor_sync(0xffffffffu, rm1, 2));
        const float mn0 = fmaxf(m0r, rm0), mn1 = fmaxf(m1r, rm1);
        const float cr0 = __expf(m0r - mn0), cr1 = __expf(m1r - mn1);
        float rs0 = 0.f, rs1 = 0.f;
#pragma unroll
        for (int nt = 0; nt < 8; nt++) {
            sc[nt][0] = __expf(sc[nt][0] - mn0); rs0 += sc[nt][0];
            sc[nt][1] = __expf(sc[nt][1] - mn0); rs0 += sc[nt][1];
            sc[nt][2] = __expf(sc[nt][2] - mn1); rs1 += sc[nt][2];
            sc[nt][3] = __expf(sc[nt][3] - mn1); rs1 += sc[nt][3];
        }
        rs0 += __shfl_xor_sync(0xffffffffu, rs0, 1);
        rs0 += __shfl_xor_sync(0xffffffffu, rs0, 2);
        rs1 += __shfl_xor_sync(0xffffffffu, rs1, 1);
        rs1 += __shfl_xor_sync(0xffffffffu, rs1, 2);
        l0 = l0*cr0 + rs0;  m0r = mn0;
        l1 = l1*cr1 + rs1;  m1r = mn1;
#pragma unroll
        for (int nd = 0; nd < 8; nd++) {
            accO[nd][0] *= cr0; accO[nd][1] *= cr0;
            accO[nd][2] *= cr1; accO[nd][3] *= cr1;
        }

        // ---- O += P V (split, P frags reused from sc) ------------------
#pragma unroll
        for (int ksv = 0; ksv < 4; ksv++) {
            uint32_t aH[4], aL[4];
            aH[0] = pf2(sc[2*ksv][0],   sc[2*ksv][1]);
            aH[1] = pf2(sc[2*ksv][2],   sc[2*ksv][3]);
            aH[2] = pf2(sc[2*ksv+1][0], sc[2*ksv+1][1]);
            aH[3] = pf2(sc[2*ksv+1][2], sc[2*ksv+1][3]);
            aL[0] = plo2(sc[2*ksv][0],   sc[2*ksv][1],   aH[0]);
            aL[1] = plo2(sc[2*ksv][2],   sc[2*ksv][3],   aH[1]);
            aL[2] = plo2(sc[2*ksv+1][0], sc[2*ksv+1][1], aH[2]);
            aL[3] = plo2(sc[2*ksv+1][2], sc[2*ksv+1][3], aH[3]);
            const int kcol = ksv*16 + lhi8;
#pragma unroll
            for (int dj = 0; dj < 4; dj++) {
                const uint32_t ro = (uint32_t)((dj*16 + lrow)*SKD + kcol) * 2;
                uint32_t t[4], vh0[2], vh1[2], vl0[2], vl1[2];
                ldsm4(t, sb + (VH)*2 + ro);
                vh0[0] = t[0]; vh1[0] = t[1]; vh0[1] = t[2]; vh1[1] = t[3];
                ldsm4(t, sb + (VL)*2 + ro);
                vl0[0] = t[0]; vl1[0] = t[1]; vl0[1] = t[2]; vl1[1] = t[3];
                mma16816(accO[2*dj],   aH, vh0);
                mma16816(accO[2*dj],   aL, vh0);
                mma16816(accO[2*dj],   aH, vl0);
                mma16816(accO[2*dj+1], aH, vh1);
                mma16816(accO[2*dj+1], aL, vh1);
                mma16816(accO[2*dj+1], aH, vl1);
            }
        }
    }

    // ---- epilogue ------------------------------------------------------
    const float i0 = 1.f / l0, i1 = 1.f / l1;
#pragma unroll
    for (int nd = 0; nd < 8; nd++) {
        const int d = h*DHEAD + nd*8 + 2*ct;
        *(float2*)(g_y + (size_t)(row0*NBATCH + n)*CDIM + d) =
            make_float2(accO[nd][0]*i0, accO[nd][1]*i0);
        *(float2*)(g_y + (size_t)(row1*NBATCH + n)*CDIM + d) =
            make_float2(accO[nd][2]*i1, accO[nd][3]*i1);
    }
}

// ---------------------------------------------------------------------------
extern "C" void kernel_launch(void* const* d_in, const int* in_sizes, int n_in,
                              void* d_out, int out_size) {
    const float* q  = (const float*)d_in[0];
    const float* k  = (const float*)d_in[1];
    const float* v  = (const float*)d_in[2];
    const float* Wq = (const float*)d_in[3];
    const float* bq = (const float*)d_in[4];
    const float* Wk = (const float*)d_in[5];
    const float* bk = (const float*)d_in[6];
    const float* Wv = (const float*)d_in[7];
    const float* bv = (const float*)d_in[8];
    const float* Wo = (const float*)d_in[9];
    const float* bo = (const float*)d_in[10];
    const int* keylen = (const int*)d_in[11];
    float* out = (float*)d_out;

    cudaFuncSetAttribute(proj3_tc, cudaFuncAttributeMaxDynamicSharedMemorySize, SMEM_G);
    cudaFuncSetAttribute(oproj_tc, cudaFuncAttributeMaxDynamicSharedMemorySize, SMEM_G);
    cudaFuncSetAttribute(attn_tc,  cudaFuncAttributeMaxDynamicSharedMemorySize, SMEM_A);

    // split fp32 -> bf16 hi/lo for GEMM operands
    split_x<<<dim3(MROWS*CDIM/4/256, 1, 3), 256>>>(q, k, v);
    split_w<<<dim3(CDIM*CDIM/4/256, 1, 4), 256>>>(Wq, Wk, Wv, Wo);

    // q/k/v projections on tensor cores -> fp32 head layout
    proj3_tc<<<dim3(CDIM/128, MROWS/128, 3), 256, SMEM_G>>>(bq, bk, bv);

    // convert attention operands to bf16 split (V transposed)
    split_qk<<<dim3(NBATCH*NHEAD*TSEQ*DHEAD/4/256, 1, 2), 256>>>();
    cvt_v<<<dim3(TSEQ/64, NHEAD, NBATCH), 256>>>();

    // tensor-core masked flash attention -> g_y (t, n, c)
    attn_tc<<<dim3(TSEQ/BQ, NHEAD, NBATCH), 256, SMEM_A>>>(keylen);

    // split y, output projection
    split_y<<<dim3(MROWS*CDIM/4/256, 1, 1), 256>>>();
    oproj_tc<<<dim3(CDIM/128, MROWS/128, 1), 256, SMEM_G>>>(bo, out);
}